// round 14
// baseline (speedup 1.0000x reference)
#include <cuda_runtime.h>
#include <cuda_bf16.h>
#include <math.h>

#define SB 8192   // B*S tokens
#define EE 1024
#define HH 8
#define SS 2048
#define EPSV 1e-5f

// -------- device scratch --------
__device__ float g_z[SB * EE];     // tanh(x@W_ez+b)
__device__ float g_hs[SB * EE];    // recurrent states (post state-LN)
__device__ float g_h1[SB * EE];    // gelu(FFN1)
__device__ float g_wp[SB * EE];    // weighted pre-LN
__device__ float g_v2[HH * 128];
__device__ float g_cc[HH];
__device__ float g_sc[SB * HH];
__device__ __nv_bfloat16 g_xh[SB * EE],  g_xl[SB * EE];    // x split
__device__ __nv_bfloat16 g_ah[SB * EE],  g_al[SB * EE];    // hln split
__device__ __nv_bfloat16 g_gh[SB * EE],  g_gl[SB * EE];    // scaled h1 split
__device__ __nv_bfloat16 g_Wezh[EE * EE], g_Wezl[EE * EE]; // [N][K]
__device__ __nv_bfloat16 g_W2h[EE * EE],  g_W2l[EE * EE];  // [N][K]
__device__ __nv_bfloat16 g_W1h[HH * 128 * 128], g_W1l[HH * 128 * 128];

__device__ __forceinline__ void bsplit(float a, unsigned short& h, unsigned short& l) {
    __nv_bfloat16 hb = __float2bfloat16(a);
    float r = a - __bfloat162float(hb);
    __nv_bfloat16 lb = __float2bfloat16(r);
    h = __bfloat16_as_ushort(hb);
    l = __bfloat16_as_ushort(lb);
}

// warp sum via shuffle butterfly (f32 redux does NOT exist on sm_103)
__device__ __forceinline__ float wsum(float v) {
    #pragma unroll
    for (int o = 16; o > 0; o >>= 1) v += __shfl_xor_sync(0xffffffffu, v, o);
    return v;
}

// integer warp reduction: single REDUX instruction (sm_80+)
__device__ __forceinline__ int redux_s32(int v) {
    int r;
    asm("redux.sync.add.s32 %0, %1, 0xffffffff;" : "=r"(r) : "r"(v));
    return r;
}

// HW tanh (sm_75+), single MUFU op
__device__ __forceinline__ float tanhapx(float x) {
    float y;
    asm("tanh.approx.f32 %0, %1;" : "=f"(y) : "f"(x));
    return y;
}

// bare MUFU.RSQ (no refinement sequence)
__device__ __forceinline__ float rsqrtapx(float x) {
    float y;
    asm("rsqrt.approx.f32 %0, %1;" : "=f"(y) : "f"(x));
    return y;
}

__device__ __forceinline__ void cpa16(unsigned dst, const void* src) {
    asm volatile("cp.async.cg.shared.global [%0], [%1], 16;" :: "r"(dst), "l"(src));
}

// ============================================================
// elementwise fp32 -> (hi,lo) bf16 split (for x)
// ============================================================
__global__ void split_kernel(const float* __restrict__ src,
                             __nv_bfloat16* __restrict__ dh,
                             __nv_bfloat16* __restrict__ dl) {
    long long i = (long long)blockIdx.x * blockDim.x + threadIdx.x;  // per 4 elems
    float4 v = ((const float4*)src)[i];
    unsigned short h0, l0, h1, l1, h2, l2, h3, l3;
    bsplit(v.x, h0, l0); bsplit(v.y, h1, l1);
    bsplit(v.z, h2, l2); bsplit(v.w, h3, l3);
    uint2 uh, ul;
    uh.x = (unsigned)h0 | ((unsigned)h1 << 16);
    uh.y = (unsigned)h2 | ((unsigned)h3 << 16);
    ul.x = (unsigned)l0 | ((unsigned)l1 << 16);
    ul.y = (unsigned)l2 | ((unsigned)l3 << 16);
    ((uint2*)dh)[i] = uh;
    ((uint2*)dl)[i] = ul;
}

// ============================================================
// transpose + split: src [K][N] fp32 (batched) -> dst [N][K] bf16 hi/lo
// ============================================================
__global__ void tsplit_kernel(const float* __restrict__ src, int K, int N,
                              __nv_bfloat16* __restrict__ dh,
                              __nv_bfloat16* __restrict__ dl) {
    __shared__ float tile[32][33];
    long long boff = (long long)blockIdx.z * K * N;
    src += boff; dh += boff; dl += boff;
    int k0 = blockIdx.y * 32, n0 = blockIdx.x * 32;
    for (int i = threadIdx.y; i < 32; i += 8)
        tile[i][threadIdx.x] = src[(long long)(k0 + i) * N + n0 + threadIdx.x];
    __syncthreads();
    for (int i = threadIdx.y; i < 32; i += 8) {
        float v = tile[threadIdx.x][i];  // = src[k0+tx][n0+i]
        unsigned short h, l;
        bsplit(v, h, l);
        long long didx = (long long)(n0 + i) * K + k0 + threadIdx.x;
        dh[didx] = __ushort_as_bfloat16(h);
        dl[didx] = __ushort_as_bfloat16(l);
    }
}

// ============================================================
// precompute: v2[h,d] = sum_e W2[h,d,e]*w_att[e]; cc[h] = b2[h].w_att + b_att
// ============================================================
__global__ void precompute_kernel(const float* __restrict__ W2,
                                  const float* __restrict__ b2,
                                  const float* __restrict__ w_att,
                                  const float* __restrict__ b_att) {
    int lane = threadIdx.x & 31;
    int warp = threadIdx.x >> 5;
    if (blockIdx.x < 128) {
        int wg = blockIdx.x * 8 + warp;
        const float* row = W2 + (long long)wg * 1024;
        float s = 0.f;
        for (int e = lane; e < 1024; e += 32) s = fmaf(row[e], w_att[e], s);
        s = wsum(s);
        if (lane == 0) g_v2[wg] = s;
    } else {
        int h = warp;
        const float* row = b2 + h * 1024;
        float s = 0.f;
        for (int e = lane; e < 1024; e += 32) s = fmaf(row[e], w_att[e], s);
        s = wsum(s);
        if (lane == 0) g_cc[h] = s + b_att[0];
    }
}

// ============================================================
// Tensor-core GEMM (split-bf16, 3xMMA). Tile 128x128, BK=32,
// cp.async double-buffer, 8 warps (2x4), warp 64x32.
// BK=32 halves barrier/wait count vs BK=16 (tensor pipe was idling
// in the barrier shadow at 39% util).
// ============================================================
__device__ __forceinline__ void mma16816(float* c, const unsigned* a, const unsigned* b) {
    asm volatile(
        "mma.sync.aligned.m16n8k16.row.col.f32.bf16.bf16.f32 "
        "{%0,%1,%2,%3}, {%4,%5,%6,%7}, {%8,%9}, {%0,%1,%2,%3};\n"
        : "+f"(c[0]), "+f"(c[1]), "+f"(c[2]), "+f"(c[3])
        : "r"(a[0]), "r"(a[1]), "r"(a[2]), "r"(a[3]), "r"(b[0]), "r"(b[1]));
}

#define SMS 40  // smem row stride in bf16 elems (32 data + 8 pad) -> conflict-free

template <int MODE>
__global__ __launch_bounds__(256, 2)
void bgemm_k(const __nv_bfloat16* __restrict__ Ah, const __nv_bfloat16* __restrict__ Al,
             int lda, long long sAz,
             const __nv_bfloat16* __restrict__ Bh, const __nv_bfloat16* __restrict__ Bl,
             int ldb, long long sBz,
             float* __restrict__ C, int ldc, long long sCz,
             int K,
             const float* __restrict__ bias, long long sbz,
             const float* __restrict__ b2, const float* __restrict__ sarr) {
    Ah += (long long)blockIdx.z * sAz;  Al += (long long)blockIdx.z * sAz;
    Bh += (long long)blockIdx.z * sBz;  Bl += (long long)blockIdx.z * sBz;
    C  += (long long)blockIdx.z * sCz;
    if (MODE != 2) bias += (long long)blockIdx.z * sbz;

    const int m0 = blockIdx.y * 128, n0 = blockIdx.x * 128;

    __shared__ __nv_bfloat16 As[2][2][128 * SMS];  // [buf][hi/lo]
    __shared__ __nv_bfloat16 Bs[2][2][128 * SMS];

    const int tid = threadIdx.x;
    const int wid = tid >> 5, lane = tid & 31;
    const int wm = wid >> 2, wn = wid & 3;       // 2 x 4 warp grid
    const int gid = lane >> 2, tig = lane & 3;

    const int ldrow = tid >> 1;
    const int ldcol = (tid & 1) * 8;             // col in {0,8}; +16 for 2nd chunk
    const long long aoff = (long long)(m0 + ldrow) * lda + ldcol;
    const long long boff = (long long)(n0 + ldrow) * ldb + ldcol;
    const int srow = ldrow * SMS + ldcol;

    unsigned dA[2][2], dB[2][2];
    #pragma unroll
    for (int bfi = 0; bfi < 2; bfi++) {
        dA[bfi][0] = (unsigned)__cvta_generic_to_shared(&As[bfi][0][srow]);
        dA[bfi][1] = (unsigned)__cvta_generic_to_shared(&As[bfi][1][srow]);
        dB[bfi][0] = (unsigned)__cvta_generic_to_shared(&Bs[bfi][0][srow]);
        dB[bfi][1] = (unsigned)__cvta_generic_to_shared(&Bs[bfi][1][srow]);
    }

    float acc[4][4][4];
    #pragma unroll
    for (int i = 0; i < 4; i++)
        #pragma unroll
        for (int j = 0; j < 4; j++)
            #pragma unroll
            for (int q = 0; q < 4; q++) acc[i][j][q] = 0.f;

    const int nk = K / 32;

    // prologue: async-load tile 0 (2 x 16B per thread per array)
    cpa16(dA[0][0], Ah + aoff);       cpa16(dA[0][0] + 32, Ah + aoff + 16);
    cpa16(dA[0][1], Al + aoff);       cpa16(dA[0][1] + 32, Al + aoff + 16);
    cpa16(dB[0][0], Bh + boff);       cpa16(dB[0][0] + 32, Bh + boff + 16);
    cpa16(dB[0][1], Bl + boff);       cpa16(dB[0][1] + 32, Bl + boff + 16);
    asm volatile("cp.async.commit_group;");
    asm volatile("cp.async.wait_group 0;");
    __syncthreads();

    int buf = 0;
    for (int kt = 0; kt < nk; kt++) {
        if (kt + 1 < nk) {
            long long ka = aoff + (kt + 1) * 32;
            long long kb = boff + (kt + 1) * 32;
            int ob = buf ^ 1;
            cpa16(dA[ob][0], Ah + ka);     cpa16(dA[ob][0] + 32, Ah + ka + 16);
            cpa16(dA[ob][1], Al + ka);     cpa16(dA[ob][1] + 32, Al + ka + 16);
            cpa16(dB[ob][0], Bh + kb);     cpa16(dB[ob][0] + 32, Bh + kb + 16);
            cpa16(dB[ob][1], Bl + kb);     cpa16(dB[ob][1] + 32, Bl + kb + 16);
            asm volatile("cp.async.commit_group;");
        }

        const __nv_bfloat16* Ash = &As[buf][0][0];
        const __nv_bfloat16* Asl = &As[buf][1][0];
        const __nv_bfloat16* Bsh = &Bs[buf][0][0];
        const __nv_bfloat16* Bsl = &Bs[buf][1][0];

        #pragma unroll
        for (int ks = 0; ks < 32; ks += 16) {
            unsigned af[4][4], bfh[4][2], bfl[4][2];
            #pragma unroll
            for (int im = 0; im < 4; im++) {
                int r0 = (wm * 64 + im * 16 + gid) * SMS + ks;
                int r1 = r0 + 8 * SMS;
                af[im][0] = *(const unsigned*)(Ash + r0 + 2 * tig);
                af[im][1] = *(const unsigned*)(Ash + r1 + 2 * tig);
                af[im][2] = *(const unsigned*)(Ash + r0 + 8 + 2 * tig);
                af[im][3] = *(const unsigned*)(Ash + r1 + 8 + 2 * tig);
            }
            #pragma unroll
            for (int jn = 0; jn < 4; jn++) {
                int c0 = (wn * 32 + jn * 8 + gid) * SMS + ks;
                bfh[jn][0] = *(const unsigned*)(Bsh + c0 + 2 * tig);
                bfh[jn][1] = *(const unsigned*)(Bsh + c0 + 8 + 2 * tig);
                bfl[jn][0] = *(const unsigned*)(Bsl + c0 + 2 * tig);
                bfl[jn][1] = *(const unsigned*)(Bsl + c0 + 8 + 2 * tig);
            }
            #pragma unroll
            for (int im = 0; im < 4; im++)
                #pragma unroll
                for (int jn = 0; jn < 4; jn++) {
                    mma16816(acc[im][jn], af[im], bfh[jn]);
                    mma16816(acc[im][jn], af[im], bfl[jn]);
                }
            #pragma unroll
            for (int im = 0; im < 4; im++) {
                int r0 = (wm * 64 + im * 16 + gid) * SMS + ks;
                int r1 = r0 + 8 * SMS;
                af[im][0] = *(const unsigned*)(Asl + r0 + 2 * tig);
                af[im][1] = *(const unsigned*)(Asl + r1 + 2 * tig);
                af[im][2] = *(const unsigned*)(Asl + r0 + 8 + 2 * tig);
                af[im][3] = *(const unsigned*)(Asl + r1 + 8 + 2 * tig);
            }
            #pragma unroll
            for (int im = 0; im < 4; im++)
                #pragma unroll
                for (int jn = 0; jn < 4; jn++)
                    mma16816(acc[im][jn], af[im], bfh[jn]);
        }

        if (kt + 1 < nk) asm volatile("cp.async.wait_group 0;");
        __syncthreads();
        buf ^= 1;
    }

    // ---------------- epilogue ----------------
    #pragma unroll
    for (int im = 0; im < 4; im++) {
        #pragma unroll
        for (int p = 0; p < 2; p++) {
            int m = m0 + wm * 64 + im * 16 + gid + p * 8;
            float sv[8];
            if (MODE == 2) {
                #pragma unroll
                for (int h = 0; h < 8; h++) sv[h] = sarr[m * 8 + h];
            }
            #pragma unroll
            for (int jn = 0; jn < 4; jn++) {
                int c = n0 + wn * 32 + jn * 8 + 2 * tig;
                float2 o;
                #pragma unroll
                for (int q = 0; q < 2; q++) {
                    float v = acc[im][jn][p * 2 + q];
                    if (MODE == 0) {
                        v = tanhf(v + bias[c + q]);
                    } else if (MODE == 1) {
                        v += bias[c + q];
                        v = v * normcdff(v);
                    } else {
                        float bb = 0.f;
                        #pragma unroll
                        for (int h = 0; h < 8; h++)
                            bb = fmaf(sv[h], b2[h * 1024 + c + q], bb);
                        v += bb;
                    }
                    if (q == 0) o.x = v; else o.y = v;
                }
                *(float2*)(C + (long long)m * ldc + c) = o;
            }
        }
    }
}

// ============================================================
// Sequential scan v8: 32-lane chains, 4 elems/lane, unrolled x8.
// cp.async smem ring (distance 6). REDUX.s32 fixed-point reduction
// with FLOAT-DOMAIN decode (magic-subtract; no I2F on critical path).
// tanh.approx gate; rsqrt.approx LN.
// ============================================================
__global__ void scan_kernel(const float* __restrict__ U_h, const float* __restrict__ U_z,
                            const float* __restrict__ b_u,
                            const float* __restrict__ lns_g, const float* __restrict__ lns_b) {
    __shared__ float ring[8][128];
    int chain = blockIdx.x;
    int bb = chain >> 3, h = chain & 7;
    int lane = threadIdx.x;

    const float MAGIC = 12582912.f;            // 1.5 * 2^23, bits 0x4B400000
    const int   BIAS31 = (int)0x1CC00000u;     // (31 * 0x4B400000) mod 2^32
    const float S0F = 8192.f,  S0I = 1.0f / (8192.f * 128.f);   // sum-x scale
    const float S1F = 4096.f,  S1I = 1.0f / (4096.f * 128.f);   // sum-x^2 scale

    float a1h[4], a2h[4], buh[4], lg[4], lb[4];
    #pragma unroll
    for (int j = 0; j < 4; j++) {
        int d = lane * 4 + j;
        a1h[j] = 0.5f * U_h[(h * 128 + d) * 128 + d];
        a2h[j] = 0.5f * U_z[(h * 128 + d) * 128 + d];
        buh[j] = 0.5f * b_u[h * 128 + d];
        lg[j] = lns_g[d]; lb[j] = lns_b[d];
    }

    const float* zbase = g_z + (long long)bb * SS * EE + h * 128 + lane * 4;
    float* ob = g_hs + (long long)bb * SS * EE + h * 128 + lane * 4;

    unsigned rl[8];
    #pragma unroll
    for (int s = 0; s < 8; s++)
        rl[s] = (unsigned)__cvta_generic_to_shared(&ring[s][lane * 4]);

    // prologue: stage 0..5 into ring, one commit group each
    #pragma unroll
    for (int s = 0; s < 6; s++) {
        cpa16(rl[s], zbase + (long long)s * EE);
        asm volatile("cp.async.commit_group;");
    }
    asm volatile("cp.async.wait_group 5;");  // stage 0 complete
    float4 zc4 = *(const float4*)&ring[0][lane * 4];
    float zv[4] = {zc4.x, zc4.y, zc4.z, zc4.w};
    float czh[4];
    #pragma unroll
    for (int j = 0; j < 4; j++) czh[j] = fmaf(zv[j], a2h[j], buh[j]);

    float hs[4] = {0.f, 0.f, 0.f, 0.f};

    for (int tb = 0; tb < SS; tb += 8) {
        #pragma unroll
        for (int u = 0; u < 8; u++) {
            const int t = tb + u;
            // prefetch stage t+6 into slot (u+6)&7 (compile-time const)
            int spf = t + 6 < SS ? t + 6 : SS - 1;
            cpa16(rl[(u + 6) & 7], zbase + (long long)spf * EE);
            asm volatile("cp.async.commit_group;");
            asm volatile("cp.async.wait_group 5;");
            float4 p4 = *(const float4*)&ring[(u + 1) & 7][lane * 4];

            // gate: tt = hs*a1h + czh ; sigmoid via tanh identity
            float x[4];
            #pragma unroll
            for (int j = 0; j < 4; j++) {
                float tt = fmaf(hs[j], a1h[j], czh[j]);
                float th = tanhapx(tt);
                float d = 0.5f * (hs[j] - zv[j]);
                float s = 0.5f * (hs[j] + zv[j]);
                x[j] = fmaf(th, d, s);
            }
            // local pairwise partials
            float s0 = (x[0] + x[1]) + (x[2] + x[3]);
            float q01 = fmaf(x[1], x[1], x[0] * x[0]);
            float q23 = fmaf(x[3], x[3], x[2] * x[2]);
            float s1 = q01 + q23;
            // fixed-point encode + single-REDUX reduce + FLOAT decode
            int b0 = __float_as_int(fmaf(s0, S0F, MAGIC));
            int b1 = __float_as_int(fmaf(s1, S1F, MAGIC));
            int r0i = redux_s32(b0) - BIAS31;   // bits of (MAGIC + sum_fixed)
            int r1b = redux_s32(b1) - BIAS31;
            float m1 = (__int_as_float(r0i) - MAGIC) * S0I;   // mean
            float Ex2 = (__int_as_float(r1b) - MAGIC) * S1I;  // E[x^2]
            float v1 = fmaf(-m1, m1, Ex2);
            float r1 = rsqrtapx(v1 + EPSV);
            float xmlg[4];
            #pragma unroll
            for (int j = 0; j < 4; j++) xmlg[j] = lg[j] * (x[j] - m1);
            #pragma unroll
            for (int j = 0; j < 4; j++) hs[j] = fmaf(xmlg[j], r1, lb[j]);

            float4 o4;
            o4.x = hs[0]; o4.y = hs[1]; o4.z = hs[2]; o4.w = hs[3];
            *(float4*)(ob + (long long)t * EE) = o4;

            // rotate z and precompute next czh (off critical path)
            zv[0] = p4.x; zv[1] = p4.y; zv[2] = p4.z; zv[3] = p4.w;
            #pragma unroll
            for (int j = 0; j < 4; j++) czh[j] = fmaf(zv[j], a2h[j], buh[j]);
        }
    }
}

// ============================================================
// Parallel post-scan: y = os_diag * hs ; ff-LN over D ; split bf16.
// One warp per (token, head).
// ============================================================
__global__ void postln_kernel(const float* __restrict__ osr,
                              const float* __restrict__ ffg, const float* __restrict__ ffb) {
    int tok = blockIdx.x;
    int h = threadIdx.x >> 5;
    int lane = threadIdx.x & 31;
    const float inv = 1.0f / 128.0f;

    long long base = (long long)tok * EE + h * 128 + lane * 4;
    float4 hv = *(const float4*)(g_hs + base);
    float os[4], fg[4], fb[4];
    #pragma unroll
    for (int j = 0; j < 4; j++) {
        int d = lane * 4 + j;
        os[j] = osr[(h * 128 + d) * 128 + d];
        fg[j] = ffg[h * 128 + d];
        fb[j] = ffb[h * 128 + d];
    }
    float y[4] = {os[0] * hv.x, os[1] * hv.y, os[2] * hv.z, os[3] * hv.w};
    float sy = 0.f, sy2 = 0.f;
    #pragma unroll
    for (int j = 0; j < 4; j++) {
        sy += y[j];
        sy2 = fmaf(y[j], y[j], sy2);
    }
    sy = wsum(sy);
    sy2 = wsum(sy2);
    float m2 = sy * inv;
    float v2 = fmaf(-m2, m2, sy2 * inv);
    float r2 = rsqrtf(v2 + EPSV);

    unsigned short oh[4], ol[4];
    #pragma unroll
    for (int j = 0; j < 4; j++) {
        float ov = fmaf(fg[j], (y[j] - m2) * r2, fb[j]);
        bsplit(ov, oh[j], ol[j]);
    }
    uint2 uh, ul;
    uh.x = (unsigned)oh[0] | ((unsigned)oh[1] << 16);
    uh.y = (unsigned)oh[2] | ((unsigned)oh[3] << 16);
    ul.x = (unsigned)ol[0] | ((unsigned)ol[1] << 16);
    ul.y = (unsigned)ol[2] | ((unsigned)ol[3] << 16);
    *(uint2*)(g_ah + base) = uh;
    *(uint2*)(g_al + base) = ul;
}

// ============================================================
// Per-token attention over heads; scales h1 and writes split-bf16 g.
// ============================================================
__global__ void attn_kernel() {
    int tok = blockIdx.x;
    int wid = threadIdx.x >> 5, lane = threadIdx.x & 31;
    __shared__ float sl[8];
    const float* hv = g_h1 + (long long)tok * EE + wid * 128;
    const float* vv = g_v2 + wid * 128;
    float hvv[4];
    float dot = 0.f;
    #pragma unroll
    for (int j = 0; j < 4; j++) {
        hvv[j] = hv[lane + 32 * j];
        dot = fmaf(hvv[j], vv[lane + 32 * j], dot);
    }
    dot = wsum(dot);
    if (lane == 0) sl[wid] = dot + g_cc[wid];
    __syncthreads();
    float mx = sl[0];
    #pragma unroll
    for (int hh = 1; hh < 8; hh++) mx = fmaxf(mx, sl[hh]);
    float ee[8];
    float se = 0.f;
    #pragma unroll
    for (int hh = 0; hh < 8; hh++) {
        ee[hh] = __expf(sl[hh] - mx);
        se += ee[hh];
    }
    float rse = __fdividef(1.0f, se);
    float s = ee[wid] * rse;
    long long base = (long long)tok * EE + wid * 128;
    #pragma unroll
    for (int j = 0; j < 4; j++) {
        float v = hvv[j] * s;
        unsigned short h, l;
        bsplit(v, h, l);
        g_gh[base + lane + 32 * j] = __ushort_as_bfloat16(h);
        g_gl[base + lane + 32 * j] = __ushort_as_bfloat16(l);
    }
    if (threadIdx.x < 8) g_sc[tok * 8 + threadIdx.x] = ee[threadIdx.x] * rse;
}

// ============================================================
// Final LayerNorm over E=1024 per token
// ============================================================
__global__ void lnout_kernel(const float* __restrict__ g, const float* __restrict__ b,
                             float* __restrict__ out) {
    int tok = blockIdx.x;
    int tid = threadIdx.x;
    const float* base = g_wp + (long long)tok * EE;
    float4 x = *(const float4*)(base + tid * 4);
    float s = x.x + x.y + x.z + x.w;
    float q = x.x * x.x + x.y * x.y + x.z * x.z + x.w * x.w;
    __shared__ float ws[8], wq[8];
    s = wsum(s);
    q = wsum(q);
    int wid = tid >> 5, lane = tid & 31;
    if (lane == 0) { ws[wid] = s; wq[wid] = q; }
    __syncthreads();
    if (tid == 0) {
        float S = 0.f, Q = 0.f;
        #pragma unroll
        for (int i = 0; i < 8; i++) { S += ws[i]; Q += wq[i]; }
        ws[0] = S; wq[0] = Q;
    }
    __syncthreads();
    float m = ws[0] * (1.0f / 1024.0f);
    float v = wq[0] * (1.0f / 1024.0f) - m * m;
    float r = rsqrtf(v + EPSV);
    float4 gg = *(const float4*)(g + tid * 4);
    float4 bb = *(const float4*)(b + tid * 4);
    float4 o4;
    o4.x = fmaf((x.x - m) * r, gg.x, bb.x);
    o4.y = fmaf((x.y - m) * r, gg.y, bb.y);
    o4.z = fmaf((x.z - m) * r, gg.z, bb.z);
    o4.w = fmaf((x.w - m) * r, gg.w, bb.w);
    *(float4*)(out + (long long)tok * EE + tid * 4) = o4;
}

// ============================================================
extern "C" void kernel_launch(void* const* d_in, const int* in_sizes, int n_in,
                              void* d_out, int out_size) {
    const float* x      = (const float*)d_in[0];
    const float* W_ez   = (const float*)d_in[1];
    const float* b_ez   = (const float*)d_in[2];
    const float* U_h    = (const float*)d_in[3];
    const float* U_z    = (const float*)d_in[4];
    const float* b_u    = (const float*)d_in[5];
    const float* osr    = (const float*)d_in[6];
    const float* lns_g  = (const float*)d_in[7];
    const float* lns_b  = (const float*)d_in[8];
    const float* ff_g   = (const float*)d_in[9];
    const float* ff_b   = (const float*)d_in[10];
    const float* ff_W1  = (const float*)d_in[11];
    const float* ff_b1  = (const float*)d_in[12];
    const float* ff_W2  = (const float*)d_in[13];
    const float* ff_b2  = (const float*)d_in[14];
    const float* w_att  = (const float*)d_in[15];
    const float* b_att  = (const float*)d_in[16];
    const float* lno_g  = (const float*)d_in[17];
    const float* lno_b  = (const float*)d_in[18];

    void *pz, *ph1, *pwp, *psc;
    void *pxh, *pxl, *pah, *pal, *pgh, *pgl;
    void *pWeh, *pWel, *pW2h, *pW2l, *pW1h, *pW1l;
    cudaGetSymbolAddress(&pz, g_z);
    cudaGetSymbolAddress(&ph1, g_h1);
    cudaGetSymbolAddress(&pwp, g_wp);
    cudaGetSymbolAddress(&psc, g_sc);
    cudaGetSymbolAddress(&pxh, g_xh);  cudaGetSymbolAddress(&pxl, g_xl);
    cudaGetSymbolAddress(&pah, g_ah);  cudaGetSymbolAddress(&pal, g_al);
    cudaGetSymbolAddress(&pgh, g_gh);  cudaGetSymbolAddress(&pgl, g_gl);
    cudaGetSymbolAddress(&pWeh, g_Wezh);  cudaGetSymbolAddress(&pWel, g_Wezl);
    cudaGetSymbolAddress(&pW2h, g_W2h);   cudaGetSymbolAddress(&pW2l, g_W2l);
    cudaGetSymbolAddress(&pW1h, g_W1h);   cudaGetSymbolAddress(&pW1l, g_W1l);

    // (1) x split, (2) W_ez tsplit, (3) W1 tsplit -> (4) GEMM0 (profiled) -> (5) SCAN
    split_kernel<<<SB * EE / 4 / 256, 256>>>(x, (__nv_bfloat16*)pxh, (__nv_bfloat16*)pxl);
    tsplit_kernel<<<dim3(32, 32, 1), dim3(32, 8)>>>(W_ez, 1024, 1024,
                                                    (__nv_bfloat16*)pWeh, (__nv_bfloat16*)pWel);
    tsplit_kernel<<<dim3(4, 4, 8), dim3(32, 8)>>>(ff_W1, 128, 128,
                                                  (__nv_bfloat16*)pW1h, (__nv_bfloat16*)pW1l);
    bgemm_k<0><<<dim3(8, 64, 1), 256>>>((__nv_bfloat16*)pxh, (__nv_bfloat16*)pxl, 1024, 0,
                                        (__nv_bfloat16*)pWeh, (__nv_bfloat16*)pWel, 1024, 0,
                                        (float*)pz, 1024, 0, 1024, b_ez, 0, nullptr, nullptr);
    scan_kernel<<<32, 32>>>(U_h, U_z, b_u, lns_g, lns_b);

    // remaining prep (independent of scan)
    tsplit_kernel<<<dim3(32, 32, 1), dim3(32, 8)>>>(ff_W2, 1024, 1024,
                                                    (__nv_bfloat16*)pW2h, (__nv_bfloat16*)pW2l);
    precompute_kernel<<<129, 256>>>(ff_W2, ff_b2, w_att, b_att);

    // parallel: y = os*hs, ff-LN, split
    postln_kernel<<<8192, 256>>>(osr, ff_g, ff_b);

    // h1 = gelu(hln @ W1[h] + b1[h])
    bgemm_k<1><<<dim3(1, 64, 8), 256>>>((__nv_bfloat16*)pah, (__nv_bfloat16*)pal, 1024, 128,
                                        (__nv_bfloat16*)pW1h, (__nv_bfloat16*)pW1l, 128, 16384,
                                        (float*)ph1, 1024, 128, 128, ff_b1, 128, nullptr, nullptr);

    // softmax scores + scale h1 -> g (split)
    attn_kernel<<<8192, 256>>>();

    // weighted = g @ W2_flat + sum_h s_h * b2[h]
    bgemm_k<2><<<dim3(8, 64, 1), 256>>>((__nv_bfloat16*)pgh, (__nv_bfloat16*)pgl, 1024, 0,
                                        (__nv_bfloat16*)pW2h, (__nv_bfloat16*)pW2l, 1024, 0,
                                        (float*)pwp, 1024, 0, 1024, nullptr, 0, ff_b2, (float*)psc);

    // final LN
    lnout_kernel<<<8192, 256>>>(lno_g, lno_b, (float*)d_out);
}

// round 16
// speedup vs baseline: 1.2083x; 1.2083x over previous
#include <cuda_runtime.h>
#include <cuda_fp16.h>
#include <math.h>

#define SB 8192   // B*S tokens
#define EE 1024
#define HH 8
#define SS 2048
#define EPSV 1e-5f

// -------- device scratch --------
__device__ float g_z[SB * EE];     // tanh(x@W_ez+b)
__device__ float g_hs[SB * EE];    // recurrent states (post state-LN)
__device__ float g_h1[SB * EE];    // gelu(FFN1)
__device__ float g_wp[SB * EE];    // weighted pre-LN
__device__ float g_v2[HH * 128];
__device__ float g_cc[HH];
__device__ float g_sc[SB * HH];
__device__ __half g_xa[SB * EE];   // x as fp16 (A-side, hi only)
__device__ __half g_aa[SB * EE];   // hln fp16
__device__ __half g_ga[SB * EE];   // scaled h1 fp16
__device__ __half g_Wezh[EE * EE], g_Wezl[EE * EE]; // [N][K] hi/lo
__device__ __half g_W2h[EE * EE],  g_W2l[EE * EE];  // [N][K]
__device__ __half g_W1h[HH * 128 * 128], g_W1l[HH * 128 * 128];

__device__ __forceinline__ void hsplit(float a, unsigned short& h, unsigned short& l) {
    __half hb = __float2half_rn(a);
    float r = a - __half2float(hb);
    __half lb = __float2half_rn(r);
    h = __half_as_ushort(hb);
    l = __half_as_ushort(lb);
}

// warp sum via shuffle butterfly (f32 redux does NOT exist on sm_103)
__device__ __forceinline__ float wsum(float v) {
    #pragma unroll
    for (int o = 16; o > 0; o >>= 1) v += __shfl_xor_sync(0xffffffffu, v, o);
    return v;
}

// integer warp reduction: single REDUX instruction (sm_80+)
__device__ __forceinline__ int redux_s32(int v) {
    int r;
    asm("redux.sync.add.s32 %0, %1, 0xffffffff;" : "=r"(r) : "r"(v));
    return r;
}

// HW tanh (sm_75+), single MUFU op
__device__ __forceinline__ float tanhapx(float x) {
    float y;
    asm("tanh.approx.f32 %0, %1;" : "=f"(y) : "f"(x));
    return y;
}

// bare MUFU.RSQ
__device__ __forceinline__ float rsqrtapx(float x) {
    float y;
    asm("rsqrt.approx.f32 %0, %1;" : "=f"(y) : "f"(x));
    return y;
}

__device__ __forceinline__ void cpa16(unsigned dst, const void* src) {
    asm volatile("cp.async.cg.shared.global [%0], [%1], 16;" :: "r"(dst), "l"(src));
}

// ============================================================
// elementwise fp32 -> fp16 (A-side activations; hi only)
// ============================================================
__global__ void tohalf_kernel(const float* __restrict__ src,
                              __half* __restrict__ dst) {
    long long i = (long long)blockIdx.x * blockDim.x + threadIdx.x;  // per 4 elems
    float4 v = ((const float4*)src)[i];
    __half2 a = __floats2half2_rn(v.x, v.y);
    __half2 b = __floats2half2_rn(v.z, v.w);
    uint2 u;
    u.x = *(unsigned*)&a;
    u.y = *(unsigned*)&b;
    ((uint2*)dst)[i] = u;
}

// ============================================================
// transpose + split: src [K][N] fp32 (batched) -> dst [N][K] fp16 hi/lo
// ============================================================
__global__ void tsplit_kernel(const float* __restrict__ src, int K, int N,
                              __half* __restrict__ dh,
                              __half* __restrict__ dl) {
    __shared__ float tile[32][33];
    long long boff = (long long)blockIdx.z * K * N;
    src += boff; dh += boff; dl += boff;
    int k0 = blockIdx.y * 32, n0 = blockIdx.x * 32;
    for (int i = threadIdx.y; i < 32; i += 8)
        tile[i][threadIdx.x] = src[(long long)(k0 + i) * N + n0 + threadIdx.x];
    __syncthreads();
    for (int i = threadIdx.y; i < 32; i += 8) {
        float v = tile[threadIdx.x][i];  // = src[k0+tx][n0+i]
        unsigned short h, l;
        hsplit(v, h, l);
        long long didx = (long long)(n0 + i) * K + k0 + threadIdx.x;
        dh[didx] = __ushort_as_half(h);
        dl[didx] = __ushort_as_half(l);
    }
}

// ============================================================
// precompute: v2[h,d] = sum_e W2[h,d,e]*w_att[e]; cc[h] = b2[h].w_att + b_att
// ============================================================
__global__ void precompute_kernel(const float* __restrict__ W2,
                                  const float* __restrict__ b2,
                                  const float* __restrict__ w_att,
                                  const float* __restrict__ b_att) {
    int lane = threadIdx.x & 31;
    int warp = threadIdx.x >> 5;
    if (blockIdx.x < 128) {
        int wg = blockIdx.x * 8 + warp;
        const float* row = W2 + (long long)wg * 1024;
        float s = 0.f;
        for (int e = lane; e < 1024; e += 32) s = fmaf(row[e], w_att[e], s);
        s = wsum(s);
        if (lane == 0) g_v2[wg] = s;
    } else {
        int h = warp;
        const float* row = b2 + h * 1024;
        float s = 0.f;
        for (int e = lane; e < 1024; e += 32) s = fmaf(row[e], w_att[e], s);
        s = wsum(s);
        if (lane == 0) g_cc[h] = s + b_att[0];
    }
}

// ============================================================
// Tensor-core GEMM, fp16 2-term split: C = Ah*Bh + Ah*Bl.
// A = fp16 activations (hi only), B = fp16 weight hi/lo.
// Tile 128x128, BK=32, cp.async double-buffer, 8 warps, warp 64x32.
// MODE 0: tanh(.+bias); MODE 1: gelu(.+bias); MODE 2: plain.
// ============================================================
__device__ __forceinline__ void mma_h(float* c, const unsigned* a, const unsigned* b) {
    asm volatile(
        "mma.sync.aligned.m16n8k16.row.col.f32.f16.f16.f32 "
        "{%0,%1,%2,%3}, {%4,%5,%6,%7}, {%8,%9}, {%0,%1,%2,%3};\n"
        : "+f"(c[0]), "+f"(c[1]), "+f"(c[2]), "+f"(c[3])
        : "r"(a[0]), "r"(a[1]), "r"(a[2]), "r"(a[3]), "r"(b[0]), "r"(b[1]));
}

#define SMS 40  // smem row stride in halves (32 data + 8 pad) -> conflict-free

template <int MODE>
__global__ __launch_bounds__(256, 2)
void hgemm_k(const __half* __restrict__ A, int lda, long long sAz,
             const __half* __restrict__ Bh, const __half* __restrict__ Bl,
             int ldb, long long sBz,
             float* __restrict__ C, int ldc, long long sCz,
             int K,
             const float* __restrict__ bias, long long sbz) {
    A  += (long long)blockIdx.z * sAz;
    Bh += (long long)blockIdx.z * sBz;  Bl += (long long)blockIdx.z * sBz;
    C  += (long long)blockIdx.z * sCz;
    if (MODE != 2) bias += (long long)blockIdx.z * sbz;

    const int m0 = blockIdx.y * 128, n0 = blockIdx.x * 128;

    __shared__ __half As[2][128 * SMS];
    __shared__ __half Bsh[2][128 * SMS];
    __shared__ __half Bsl[2][128 * SMS];

    const int tid = threadIdx.x;
    const int wid = tid >> 5, lane = tid & 31;
    const int wm = wid >> 2, wn = wid & 3;       // 2 x 4 warp grid
    const int gid = lane >> 2, tig = lane & 3;

    const int ldrow = tid >> 1;
    const int ldcol = (tid & 1) * 8;             // +16 for 2nd chunk
    const long long aoff = (long long)(m0 + ldrow) * lda + ldcol;
    const long long boff = (long long)(n0 + ldrow) * ldb + ldcol;
    const int srow = ldrow * SMS + ldcol;

    unsigned dA[2], dBh[2], dBl[2];
    #pragma unroll
    for (int bfi = 0; bfi < 2; bfi++) {
        dA[bfi]  = (unsigned)__cvta_generic_to_shared(&As[bfi][srow]);
        dBh[bfi] = (unsigned)__cvta_generic_to_shared(&Bsh[bfi][srow]);
        dBl[bfi] = (unsigned)__cvta_generic_to_shared(&Bsl[bfi][srow]);
    }

    float acc[4][4][4];
    #pragma unroll
    for (int i = 0; i < 4; i++)
        #pragma unroll
        for (int j = 0; j < 4; j++)
            #pragma unroll
            for (int q = 0; q < 4; q++) acc[i][j][q] = 0.f;

    const int nk = K / 32;

    // prologue: async-load tile 0 (2 x 16B per thread per matrix)
    cpa16(dA[0], A + aoff);         cpa16(dA[0] + 32, A + aoff + 16);
    cpa16(dBh[0], Bh + boff);       cpa16(dBh[0] + 32, Bh + boff + 16);
    cpa16(dBl[0], Bl + boff);       cpa16(dBl[0] + 32, Bl + boff + 16);
    asm volatile("cp.async.commit_group;");
    asm volatile("cp.async.wait_group 0;");
    __syncthreads();

    int buf = 0;
    for (int kt = 0; kt < nk; kt++) {
        if (kt + 1 < nk) {
            long long ka = aoff + (kt + 1) * 32;
            long long kb = boff + (kt + 1) * 32;
            int ob = buf ^ 1;
            cpa16(dA[ob], A + ka);       cpa16(dA[ob] + 32, A + ka + 16);
            cpa16(dBh[ob], Bh + kb);     cpa16(dBh[ob] + 32, Bh + kb + 16);
            cpa16(dBl[ob], Bl + kb);     cpa16(dBl[ob] + 32, Bl + kb + 16);
            asm volatile("cp.async.commit_group;");
        }

        const __half* Ash = &As[buf][0];
        const __half* Bh_s = &Bsh[buf][0];
        const __half* Bl_s = &Bsl[buf][0];

        #pragma unroll
        for (int ks = 0; ks < 32; ks += 16) {
            unsigned af[4][4], bfh[4][2], bfl[4][2];
            #pragma unroll
            for (int im = 0; im < 4; im++) {
                int r0 = (wm * 64 + im * 16 + gid) * SMS + ks;
                int r1 = r0 + 8 * SMS;
                af[im][0] = *(const unsigned*)(Ash + r0 + 2 * tig);
                af[im][1] = *(const unsigned*)(Ash + r1 + 2 * tig);
                af[im][2] = *(const unsigned*)(Ash + r0 + 8 + 2 * tig);
                af[im][3] = *(const unsigned*)(Ash + r1 + 8 + 2 * tig);
            }
            #pragma unroll
            for (int jn = 0; jn < 4; jn++) {
                int c0 = (wn * 32 + jn * 8 + gid) * SMS + ks;
                bfh[jn][0] = *(const unsigned*)(Bh_s + c0 + 2 * tig);
                bfh[jn][1] = *(const unsigned*)(Bh_s + c0 + 8 + 2 * tig);
                bfl[jn][0] = *(const unsigned*)(Bl_s + c0 + 2 * tig);
                bfl[jn][1] = *(const unsigned*)(Bl_s + c0 + 8 + 2 * tig);
            }
            #pragma unroll
            for (int im = 0; im < 4; im++)
                #pragma unroll
                for (int jn = 0; jn < 4; jn++) {
                    mma_h(acc[im][jn], af[im], bfh[jn]);
                    mma_h(acc[im][jn], af[im], bfl[jn]);
                }
        }

        if (kt + 1 < nk) asm volatile("cp.async.wait_group 0;");
        __syncthreads();
        buf ^= 1;
    }

    // ---------------- epilogue ----------------
    #pragma unroll
    for (int im = 0; im < 4; im++) {
        #pragma unroll
        for (int p = 0; p < 2; p++) {
            int m = m0 + wm * 64 + im * 16 + gid + p * 8;
            #pragma unroll
            for (int jn = 0; jn < 4; jn++) {
                int c = n0 + wn * 32 + jn * 8 + 2 * tig;
                float2 o;
                #pragma unroll
                for (int q = 0; q < 2; q++) {
                    float v = acc[im][jn][p * 2 + q];
                    if (MODE == 0) {
                        v = tanhf(v + bias[c + q]);
                    } else if (MODE == 1) {
                        v += bias[c + q];
                        v = v * normcdff(v);  // exact GELU
                    }
                    if (q == 0) o.x = v; else o.y = v;
                }
                *(float2*)(C + (long long)m * ldc + c) = o;
            }
        }
    }
}

// ============================================================
// Sequential scan v8 (round-12 best, unchanged).
// ============================================================
__global__ void scan_kernel(const float* __restrict__ U_h, const float* __restrict__ U_z,
                            const float* __restrict__ b_u,
                            const float* __restrict__ lns_g, const float* __restrict__ lns_b) {
    __shared__ float ring[8][128];
    int chain = blockIdx.x;
    int bb = chain >> 3, h = chain & 7;
    int lane = threadIdx.x;

    const float MAGIC = 12582912.f;            // 1.5 * 2^23, bits 0x4B400000
    const int   BIAS31 = (int)0x1CC00000u;     // (31 * 0x4B400000) mod 2^32
    const float S0F = 8192.f,  S0I = 1.0f / (8192.f * 128.f);
    const float S1F = 4096.f,  S1I = 1.0f / (4096.f * 128.f);

    float a1h[4], a2h[4], buh[4], lg[4], lb[4];
    #pragma unroll
    for (int j = 0; j < 4; j++) {
        int d = lane * 4 + j;
        a1h[j] = 0.5f * U_h[(h * 128 + d) * 128 + d];
        a2h[j] = 0.5f * U_z[(h * 128 + d) * 128 + d];
        buh[j] = 0.5f * b_u[h * 128 + d];
        lg[j] = lns_g[d]; lb[j] = lns_b[d];
    }

    const float* zbase = g_z + (long long)bb * SS * EE + h * 128 + lane * 4;
    float* ob = g_hs + (long long)bb * SS * EE + h * 128 + lane * 4;

    unsigned rl[8];
    #pragma unroll
    for (int s = 0; s < 8; s++)
        rl[s] = (unsigned)__cvta_generic_to_shared(&ring[s][lane * 4]);

    #pragma unroll
    for (int s = 0; s < 6; s++) {
        cpa16(rl[s], zbase + (long long)s * EE);
        asm volatile("cp.async.commit_group;");
    }
    asm volatile("cp.async.wait_group 5;");
    float4 zc4 = *(const float4*)&ring[0][lane * 4];
    float zv[4] = {zc4.x, zc4.y, zc4.z, zc4.w};
    float czh[4];
    #pragma unroll
    for (int j = 0; j < 4; j++) czh[j] = fmaf(zv[j], a2h[j], buh[j]);

    float hs[4] = {0.f, 0.f, 0.f, 0.f};

    for (int tb = 0; tb < SS; tb += 8) {
        #pragma unroll
        for (int u = 0; u < 8; u++) {
            const int t = tb + u;
            int spf = t + 6 < SS ? t + 6 : SS - 1;
            cpa16(rl[(u + 6) & 7], zbase + (long long)spf * EE);
            asm volatile("cp.async.commit_group;");
            asm volatile("cp.async.wait_group 5;");
            float4 p4 = *(const float4*)&ring[(u + 1) & 7][lane * 4];

            float x[4];
            #pragma unroll
            for (int j = 0; j < 4; j++) {
                float tt = fmaf(hs[j], a1h[j], czh[j]);
                float th = tanhapx(tt);
                float d = 0.5f * (hs[j] - zv[j]);
                float s = 0.5f * (hs[j] + zv[j]);
                x[j] = fmaf(th, d, s);
            }
            float s0 = (x[0] + x[1]) + (x[2] + x[3]);
            float q01 = fmaf(x[1], x[1], x[0] * x[0]);
            float q23 = fmaf(x[3], x[3], x[2] * x[2]);
            float s1 = q01 + q23;
            int b0 = __float_as_int(fmaf(s0, S0F, MAGIC));
            int b1 = __float_as_int(fmaf(s1, S1F, MAGIC));
            int r0i = redux_s32(b0) - BIAS31;
            int r1b = redux_s32(b1) - BIAS31;
            float m1 = (__int_as_float(r0i) - MAGIC) * S0I;
            float Ex2 = (__int_as_float(r1b) - MAGIC) * S1I;
            float v1 = fmaf(-m1, m1, Ex2);
            float r1 = rsqrtapx(v1 + EPSV);
            float xmlg[4];
            #pragma unroll
            for (int j = 0; j < 4; j++) xmlg[j] = lg[j] * (x[j] - m1);
            #pragma unroll
            for (int j = 0; j < 4; j++) hs[j] = fmaf(xmlg[j], r1, lb[j]);

            float4 o4;
            o4.x = hs[0]; o4.y = hs[1]; o4.z = hs[2]; o4.w = hs[3];
            *(float4*)(ob + (long long)t * EE) = o4;

            zv[0] = p4.x; zv[1] = p4.y; zv[2] = p4.z; zv[3] = p4.w;
            #pragma unroll
            for (int j = 0; j < 4; j++) czh[j] = fmaf(zv[j], a2h[j], buh[j]);
        }
    }
}

// ============================================================
// Parallel post-scan: y = os_diag * hs ; ff-LN over D ; -> fp16.
// One warp per (token, head).
// ============================================================
__global__ void postln_kernel(const float* __restrict__ osr,
                              const float* __restrict__ ffg, const float* __restrict__ ffb) {
    int tok = blockIdx.x;
    int h = threadIdx.x >> 5;
    int lane = threadIdx.x & 31;
    const float inv = 1.0f / 128.0f;

    long long base = (long long)tok * EE + h * 128 + lane * 4;
    float4 hv = *(const float4*)(g_hs + base);
    float os[4], fg[4], fb[4];
    #pragma unroll
    for (int j = 0; j < 4; j++) {
        int d = lane * 4 + j;
        os[j] = osr[(h * 128 + d) * 128 + d];
        fg[j] = ffg[h * 128 + d];
        fb[j] = ffb[h * 128 + d];
    }
    float y[4] = {os[0] * hv.x, os[1] * hv.y, os[2] * hv.z, os[3] * hv.w};
    float sy = 0.f, sy2 = 0.f;
    #pragma unroll
    for (int j = 0; j < 4; j++) {
        sy += y[j];
        sy2 = fmaf(y[j], y[j], sy2);
    }
    sy = wsum(sy);
    sy2 = wsum(sy2);
    float m2 = sy * inv;
    float v2 = fmaf(-m2, m2, sy2 * inv);
    float r2 = rsqrtf(v2 + EPSV);

    __half2 o01 = __floats2half2_rn(fmaf(fg[0], (y[0] - m2) * r2, fb[0]),
                                    fmaf(fg[1], (y[1] - m2) * r2, fb[1]));
    __half2 o23 = __floats2half2_rn(fmaf(fg[2], (y[2] - m2) * r2, fb[2]),
                                    fmaf(fg[3], (y[3] - m2) * r2, fb[3]));
    uint2 u;
    u.x = *(unsigned*)&o01;
    u.y = *(unsigned*)&o23;
    *(uint2*)(g_aa + base) = u;
}

// ============================================================
// Per-token attention over heads; scales h1 and writes fp16 g.
// ============================================================
__global__ void attn_kernel() {
    int tok = blockIdx.x;
    int wid = threadIdx.x >> 5, lane = threadIdx.x & 31;
    __shared__ float sl[8];
    const float* hv = g_h1 + (long long)tok * EE + wid * 128;
    const float* vv = g_v2 + wid * 128;
    float hvv[4];
    float dot = 0.f;
    #pragma unroll
    for (int j = 0; j < 4; j++) {
        hvv[j] = hv[lane + 32 * j];
        dot = fmaf(hvv[j], vv[lane + 32 * j], dot);
    }
    dot = wsum(dot);
    if (lane == 0) sl[wid] = dot + g_cc[wid];
    __syncthreads();
    float mx = sl[0];
    #pragma unroll
    for (int hh = 1; hh < 8; hh++) mx = fmaxf(mx, sl[hh]);
    float ee[8];
    float se = 0.f;
    #pragma unroll
    for (int hh = 0; hh < 8; hh++) {
        ee[hh] = __expf(sl[hh] - mx);
        se += ee[hh];
    }
    float rse = __fdividef(1.0f, se);
    float s = ee[wid] * rse;
    long long base = (long long)tok * EE + wid * 128;
    #pragma unroll
    for (int j = 0; j < 4; j++)
        g_ga[base + lane + 32 * j] = __float2half_rn(hvv[j] * s);
    if (threadIdx.x < 8) g_sc[tok * 8 + threadIdx.x] = ee[threadIdx.x] * rse;
}

// ============================================================
// Final LayerNorm over E=1024 per token (+ sum_h s_h * b2[h][c],
// moved out of the GEMM2 epilogue).
// ============================================================
__global__ void lnout_kernel(const float* __restrict__ g, const float* __restrict__ b,
                             const float* __restrict__ b2, float* __restrict__ out) {
    int tok = blockIdx.x;
    int tid = threadIdx.x;
    float scv[8];
    #pragma unroll
    for (int h = 0; h < 8; h++) scv[h] = g_sc[tok * 8 + h];

    const float* base = g_wp + (long long)tok * EE;
    float4 x = *(const float4*)(base + tid * 4);
    #pragma unroll
    for (int h = 0; h < 8; h++) {
        float4 bv = *(const float4*)(b2 + h * 1024 + tid * 4);
        x.x = fmaf(scv[h], bv.x, x.x);
        x.y = fmaf(scv[h], bv.y, x.y);
        x.z = fmaf(scv[h], bv.z, x.z);
        x.w = fmaf(scv[h], bv.w, x.w);
    }
    float s = x.x + x.y + x.z + x.w;
    float q = x.x * x.x + x.y * x.y + x.z * x.z + x.w * x.w;
    __shared__ float ws[8], wq[8];
    s = wsum(s);
    q = wsum(q);
    int wid = tid >> 5, lane = tid & 31;
    if (lane == 0) { ws[wid] = s; wq[wid] = q; }
    __syncthreads();
    if (tid == 0) {
        float S = 0.f, Q = 0.f;
        #pragma unroll
        for (int i = 0; i < 8; i++) { S += ws[i]; Q += wq[i]; }
        ws[0] = S; wq[0] = Q;
    }
    __syncthreads();
    float m = ws[0] * (1.0f / 1024.0f);
    float v = wq[0] * (1.0f / 1024.0f) - m * m;
    float r = rsqrtf(v + EPSV);
    float4 gg = *(const float4*)(g + tid * 4);
    float4 bb = *(const float4*)(b + tid * 4);
    float4 o4;
    o4.x = fmaf((x.x - m) * r, gg.x, bb.x);
    o4.y = fmaf((x.y - m) * r, gg.y, bb.y);
    o4.z = fmaf((x.z - m) * r, gg.z, bb.z);
    o4.w = fmaf((x.w - m) * r, gg.w, bb.w);
    *(float4*)(out + (long long)tok * EE + tid * 4) = o4;
}

// ============================================================
extern "C" void kernel_launch(void* const* d_in, const int* in_sizes, int n_in,
                              void* d_out, int out_size) {
    const float* x      = (const float*)d_in[0];
    const float* W_ez   = (const float*)d_in[1];
    const float* b_ez   = (const float*)d_in[2];
    const float* U_h    = (const float*)d_in[3];
    const float* U_z    = (const float*)d_in[4];
    const float* b_u    = (const float*)d_in[5];
    const float* osr    = (const float*)d_in[6];
    const float* lns_g  = (const float*)d_in[7];
    const float* lns_b  = (const float*)d_in[8];
    const float* ff_g   = (const float*)d_in[9];
    const float* ff_b   = (const float*)d_in[10];
    const float* ff_W1  = (const float*)d_in[11];
    const float* ff_b1  = (const float*)d_in[12];
    const float* ff_W2  = (const float*)d_in[13];
    const float* ff_b2  = (const float*)d_in[14];
    const float* w_att  = (const float*)d_in[15];
    const float* b_att  = (const float*)d_in[16];
    const float* lno_g  = (const float*)d_in[17];
    const float* lno_b  = (const float*)d_in[18];

    void *pz, *ph1, *pwp;
    void *pxa, *paa, *pga;
    void *pWeh, *pWel, *pW2h, *pW2l, *pW1h, *pW1l;
    cudaGetSymbolAddress(&pz, g_z);
    cudaGetSymbolAddress(&ph1, g_h1);
    cudaGetSymbolAddress(&pwp, g_wp);
    cudaGetSymbolAddress(&pxa, g_xa);
    cudaGetSymbolAddress(&paa, g_aa);
    cudaGetSymbolAddress(&pga, g_ga);
    cudaGetSymbolAddress(&pWeh, g_Wezh);  cudaGetSymbolAddress(&pWel, g_Wezl);
    cudaGetSymbolAddress(&pW2h, g_W2h);   cudaGetSymbolAddress(&pW2l, g_W2l);
    cudaGetSymbolAddress(&pW1h, g_W1h);   cudaGetSymbolAddress(&pW1l, g_W1l);

    // (1) x->fp16, (2) W_ez tsplit, (3) W1 tsplit -> (4) GEMM0 (profiled) -> (5) SCAN
    tohalf_kernel<<<SB * EE / 4 / 256, 256>>>(x, (__half*)pxa);
    tsplit_kernel<<<dim3(32, 32, 1), dim3(32, 8)>>>(W_ez, 1024, 1024,
                                                    (__half*)pWeh, (__half*)pWel);
    tsplit_kernel<<<dim3(4, 4, 8), dim3(32, 8)>>>(ff_W1, 128, 128,
                                                  (__half*)pW1h, (__half*)pW1l);
    hgemm_k<0><<<dim3(8, 64, 1), 256>>>((__half*)pxa, 1024, 0,
                                        (__half*)pWeh, (__half*)pWel, 1024, 0,
                                        (float*)pz, 1024, 0, 1024, b_ez, 0);
    scan_kernel<<<32, 32>>>(U_h, U_z, b_u, lns_g, lns_b);

    // remaining prep (independent of scan)
    tsplit_kernel<<<dim3(32, 32, 1), dim3(32, 8)>>>(ff_W2, 1024, 1024,
                                                    (__half*)pW2h, (__half*)pW2l);
    precompute_kernel<<<129, 256>>>(ff_W2, ff_b2, w_att, b_att);

    // parallel: y = os*hs, ff-LN -> fp16
    postln_kernel<<<8192, 256>>>(osr, ff_g, ff_b);

    // h1 = gelu(hln @ W1[h] + b1[h])
    hgemm_k<1><<<dim3(1, 64, 8), 256>>>((__half*)paa, 1024, 128,
                                        (__half*)pW1h, (__half*)pW1l, 128, 16384,
                                        (float*)ph1, 1024, 128, 128, ff_b1, 128);

    // softmax scores + scale h1 -> g (fp16)
    attn_kernel<<<8192, 256>>>();

    // weighted = g @ W2_flat (plain; score-bias added in lnout)
    hgemm_k<2><<<dim3(8, 64, 1), 256>>>((__half*)pga, 1024, 0,
                                        (__half*)pW2h, (__half*)pW2l, 1024, 0,
                                        (float*)pwp, 1024, 0, 1024, nullptr, 0);

    // final LN (+ sum_h s_h * b2[h])
    lnout_kernel<<<8192, 256>>>(lno_g, lno_b, ff_b2, (float*)d_out);
}